// round 15
// baseline (speedup 1.0000x reference)
#include <cuda_runtime.h>
#include <cuda_fp16.h>
#include <cstdint>
#include <cstddef>

typedef __half fp16;

#define BATCH 4
#define SLEN  2048
#define DIN   1024
#define NTOK  (BATCH*SLEN)

// CTA computes 64 x 256 (two 64x128 N-tiles, A reused), BK=64, 4 warps (2x2)
#define BM 64
#define BNT 128                     // per-tile N
#define BN (2*BNT)                  // CTA N span
#define BK 64
#define A_BYTES (64*128)            // 8KB
#define B_TILE (128*128)            // 16KB per B tile
#define OFF_A  0
#define OFF_B0 (A_BYTES)
#define OFF_B1 (A_BYTES + B_TILE)
#define STAGE  (A_BYTES + 2*B_TILE) // 40KB/stage, 2 stages
#define SMEM_REQ (1024 + 2*STAGE)   // ~81KB -> 2 CTAs/SM

// ---------------- scratch (device globals; no allocs allowed) ----------------
__device__ fp16 g_X[(size_t)NTOK*DIN];        // X fp16
__device__ fp16 g_WT[3][(size_t)DIN*DIN];     // W^T fp16; [0],[1] contiguous = QK merged B
__device__ fp16 g_QK[(size_t)NTOK*2*DIN];     // cols 0..1023=Q, 1024..2047=K
__device__ fp16 g_VT[(size_t)DIN*NTOK];       // V^T: [e][b*S+s]
__device__ float g_S[(size_t)BATCH*SLEN*SLEN];    // raw scores (unscaled)
__device__ fp16 g_P[(size_t)BATCH*SLEN*SLEN];     // softmax weights (zero-padded to 128)

// ---------------- helpers ----------------
__device__ __forceinline__ uint32_t smem_u32(const void* p) {
    return (uint32_t)__cvta_generic_to_shared(p);
}
#define CP_COMMIT() asm volatile("cp.async.commit_group;\n" ::: "memory")
#define CP_WAIT1()  asm volatile("cp.async.wait_group 1;\n" ::: "memory")
#define CP_WAIT0()  asm volatile("cp.async.wait_group 0;\n" ::: "memory")

__device__ __forceinline__ void ldsm4(uint32_t* r, uint32_t addr) {
    asm volatile("ldmatrix.sync.aligned.m8n8.x4.shared.b16 {%0,%1,%2,%3}, [%4];"
        : "=r"(r[0]), "=r"(r[1]), "=r"(r[2]), "=r"(r[3]) : "r"(addr));
}
__device__ __forceinline__ void mma_f16(float* d, const uint32_t* a, const uint32_t* b) {
    asm volatile(
        "mma.sync.aligned.m16n8k16.row.col.f32.f16.f16.f32 "
        "{%0,%1,%2,%3}, {%4,%5,%6,%7}, {%8,%9}, {%0,%1,%2,%3};"
        : "+f"(d[0]), "+f"(d[1]), "+f"(d[2]), "+f"(d[3])
        : "r"(a[0]), "r"(a[1]), "r"(a[2]), "r"(a[3]), "r"(b[0]), "r"(b[1]));
}

// cp.async a [ROWS x 64 fp16] panel (128B rows) into swizzled smem; 128 threads
template<int ROWS>
__device__ __forceinline__ void load_panel(const fp16* __restrict__ g, int ld,
                                           int row0, int k0, uint32_t sdst, int tid)
{
#pragma unroll
    for (int c = tid; c < ROWS * 8; c += 128) {
        int r = c >> 3, col = c & 7;
        const void* src = (const void*)(g + (size_t)(row0 + r) * ld + k0 + col * 8);
        uint32_t dst = sdst + ((uint32_t)r << 7) + ((uint32_t)(col ^ (r & 7)) << 4);
        asm volatile("cp.async.cg.shared.global [%0], [%1], 16;\n" :: "r"(dst), "l"(src));
    }
}

// load one stage: A [64 x 64] + B tile0 [128 x 64] + B tile1 [128 x 64]
__device__ __forceinline__ void load_stage(const fp16* A, const fp16* B, int lda, int ldb,
                                           int m0, int n0, int k0, uint32_t sb, int tid)
{
    load_panel<BM >(A, lda, m0, k0,        sb + OFF_A,  tid);
    load_panel<BNT>(B, ldb, n0, k0,        sb + OFF_B0, tid);
    load_panel<BNT>(B, ldb, n0 + BNT, k0,  sb + OFF_B1, tid);
}

// ---------------------------------------------------------------------------
// fp16 1-pass dual-N-tile GEMM: D[m][n] = sum_k A[m][k]*B[n][k]
// CTA covers [BM x 2*BNT]; A fragments reused across both N-tiles.
// mode 0: fp32 output; mode 2: fp16 output
// causal 0: none; 1: skip CTA if n0 > m0+BM-1 (scores);
//        3: kEnd=(by+1)*BM + load-balance remap of by (PV)
// 128 threads, warps 2m x 2n, per-tile warp tile 32x64.
// ---------------------------------------------------------------------------
__global__ void __launch_bounds__(128, 2)
gemm1h(const fp16* __restrict__ A, const fp16* __restrict__ B,
       int K, int lda, int ldb,
       long long sAz, long long sBz, long long sCz,
       float* __restrict__ Cf, fp16* __restrict__ Ch,
       int ldc, int mode, int causal)
{
    const int bx = blockIdx.x, z = blockIdx.z;
    int by = blockIdx.y;
    if (causal == 3) {
        const int n = gridDim.y;
        by = (by & 1) ? (n - 1 - (by >> 1)) : (by >> 1);
    }
    const int m0 = by * BM, n0 = bx * BN;
    if (causal == 1 && n0 > m0 + (BM - 1)) return;

    const int kEnd = (causal == 3) ? (by + 1) * BM : K;
    const int nit = kEnd / BK;

    const fp16* Ap = A + (size_t)z * sAz;
    const fp16* Bp = B + (size_t)z * sBz;

    extern __shared__ char smem_raw[];
    const uint32_t sbase = (smem_u32(smem_raw) + 1023u) & ~1023u;

    const int tid = threadIdx.x;
    const int wid = tid >> 5, lid = tid & 31;
    const int warp_m = wid >> 1;        // 0..1 (32 rows each)
    const int warp_n = wid & 1;         // 0..1 (64 cols each, per N-tile)

    float acc[2][2][8][4];              // [tile][im][j][4] = 128 regs
#pragma unroll
    for (int t = 0; t < 2; t++)
#pragma unroll
        for (int i = 0; i < 2; i++)
#pragma unroll
            for (int j = 0; j < 8; j++)
#pragma unroll
                for (int q = 0; q < 4; q++) acc[t][i][j][q] = 0.0f;

    const int a_row_base = warp_m * 32 + (lid & 15);
    const int a_chalf = lid >> 4;
    const int b_row_base = warp_n * 64 + (lid >> 4) * 8 + (lid & 7);
    const int b_chalf = (lid >> 3) & 1;

    load_stage(Ap, Bp, lda, ldb, m0, n0, 0, sbase, tid);
    CP_COMMIT();

    uint32_t ah[2][2][4];               // [buf][im][4], double-buffered across kk
    uint32_t b0[4][4], b1[4][4];        // per-tile fragments, half-kk pipelined

    for (int it = 0; it < nit; it++) {
        const int p = it & 1;
        if (it + 1 < nit) {
            load_stage(Ap, Bp, lda, ldb, m0, n0, (it + 1) * BK,
                       sbase + (p ^ 1) * STAGE, tid);
            CP_COMMIT();
            CP_WAIT1();
        } else {
            CP_WAIT0();
        }
        __syncthreads();

        const uint32_t sb = sbase + p * STAGE;

        // preload kk=0: A frags + B tile0 frags
#pragma unroll
        for (int im = 0; im < 2; im++) {
            const int row = a_row_base + im * 16;
            const uint32_t off = ((uint32_t)row << 7) + ((uint32_t)(a_chalf ^ (row & 7)) << 4);
            ldsm4(ah[0][im], sb + OFF_A + off);
        }
#pragma unroll
        for (int jn = 0; jn < 4; jn++) {
            const int n = b_row_base + jn * 16;
            const uint32_t off = ((uint32_t)n << 7) + ((uint32_t)(b_chalf ^ (n & 7)) << 4);
            ldsm4(b0[jn], sb + OFF_B0 + off);
        }

#pragma unroll
        for (int kk = 0; kk < 4; kk++) {
            const int cur = kk & 1, nxt = cur ^ 1;

            // load B tile1 fragments for this kk (consumed after tile0 MMAs)
#pragma unroll
            for (int jn = 0; jn < 4; jn++) {
                const int n = b_row_base + jn * 16;
                const int c16 = kk * 2 + b_chalf;
                const uint32_t off = ((uint32_t)n << 7) + ((uint32_t)(c16 ^ (n & 7)) << 4);
                ldsm4(b1[jn], sb + OFF_B1 + off);
            }
            // prefetch A fragments for kk+1
            if (kk < 3) {
#pragma unroll
                for (int im = 0; im < 2; im++) {
                    const int row = a_row_base + im * 16;
                    const int c16 = (kk + 1) * 2 + a_chalf;
                    const uint32_t off = ((uint32_t)row << 7) + ((uint32_t)(c16 ^ (row & 7)) << 4);
                    ldsm4(ah[nxt][im], sb + OFF_A + off);
                }
            }

            // tile0 MMAs (16)
#pragma unroll
            for (int jn = 0; jn < 4; jn++)
#pragma unroll
                for (int im = 0; im < 2; im++)
#pragma unroll
                    for (int h = 0; h < 2; h++)
                        mma_f16(acc[0][im][jn * 2 + h], ah[cur][im], b0[jn] + 2 * h);

            // load B tile0 fragments for kk+1 (consumed at next kk's tile0 MMAs)
            if (kk < 3) {
#pragma unroll
                for (int jn = 0; jn < 4; jn++) {
                    const int n = b_row_base + jn * 16;
                    const int c16 = (kk + 1) * 2 + b_chalf;
                    const uint32_t off = ((uint32_t)n << 7) + ((uint32_t)(c16 ^ (n & 7)) << 4);
                    ldsm4(b0[jn], sb + OFF_B0 + off);
                }
            }

            // tile1 MMAs (16)
#pragma unroll
            for (int jn = 0; jn < 4; jn++)
#pragma unroll
                for (int im = 0; im < 2; im++)
#pragma unroll
                    for (int h = 0; h < 2; h++)
                        mma_f16(acc[1][im][jn * 2 + h], ah[cur][im], b1[jn] + 2 * h);
        }
        __syncthreads();
    }

    // epilogue (both tiles)
    const int tq = lid >> 2;
    const int tr = lid & 3;
    const size_t cbase = (size_t)z * (size_t)sCz;
#pragma unroll
    for (int t = 0; t < 2; t++) {
#pragma unroll
        for (int im = 0; im < 2; im++) {
#pragma unroll
            for (int j = 0; j < 8; j++) {
                const int r0 = m0 + warp_m * 32 + im * 16 + tq;
                const int c0 = n0 + t * BNT + warp_n * 64 + j * 8 + tr * 2;
                const float* d = acc[t][im][j];
                if (mode == 0) {
                    *(float2*)(Cf + cbase + (size_t)r0 * ldc + c0)       = make_float2(d[0], d[1]);
                    *(float2*)(Cf + cbase + (size_t)(r0 + 8) * ldc + c0) = make_float2(d[2], d[3]);
                } else {
#pragma unroll
                    for (int rr = 0; rr < 2; rr++) {
                        __half2 hv;
                        hv.x = __float2half_rn(d[2 * rr]);
                        hv.y = __float2half_rn(d[2 * rr + 1]);
                        const size_t o = cbase + (size_t)(r0 + 8 * rr) * ldc + c0;
                        *(uint32_t*)(Ch + o) = *(uint32_t*)&hv;
                    }
                }
            }
        }
    }
}

// ---------------------------------------------------------------------------
// fp32 -> fp16 convert, elementwise (4 per thread)
// ---------------------------------------------------------------------------
__global__ void __launch_bounds__(256)
convert_h(const float* __restrict__ x, fp16* __restrict__ h16, int n4)
{
    int i = blockIdx.x * 256 + threadIdx.x;
    if (i >= n4) return;
    float4 v = ((const float4*)x)[i];
    fp16 h[4];
    h[0] = __float2half_rn(v.x);
    h[1] = __float2half_rn(v.y);
    h[2] = __float2half_rn(v.z);
    h[3] = __float2half_rn(v.w);
    ((uint2*)h16)[i] = *(uint2*)h;
}

// ---------------------------------------------------------------------------
// All three weights: W [DIN x DIN] fp32 -> W^T fp16 (z selects matrix)
// ---------------------------------------------------------------------------
__global__ void __launch_bounds__(256)
transpose3_h(const float* __restrict__ W0, const float* __restrict__ W1,
             const float* __restrict__ W2, fp16* __restrict__ T)
{
    const int zz = blockIdx.z;
    const float* W = (zz == 0) ? W0 : (zz == 1) ? W1 : W2;
    const size_t zoff = (size_t)zz * DIN * DIN;

    __shared__ float t[32][33];
    const int bx = blockIdx.x * 32, by = blockIdx.y * 32;
    const int x = threadIdx.x, y = threadIdx.y;
#pragma unroll
    for (int i = 0; i < 32; i += 8)
        t[y + i][x] = W[(size_t)(by + y + i) * DIN + bx + x];
    __syncthreads();
#pragma unroll
    for (int i = 0; i < 32; i += 8)
        T[zoff + (size_t)(bx + y + i) * DIN + by + x] = __float2half_rn(t[x][y + i]);
}

// ---------------------------------------------------------------------------
// Softmax over k<=q of scale*S, emit fp16 P, zero-pad to 128 boundary
// ---------------------------------------------------------------------------
__global__ void __launch_bounds__(256)
softmax_h(const float* __restrict__ S, fp16* __restrict__ P, float scale)
{
    const int row = blockIdx.x;
    const int q = row & (SLEN - 1);
    const float* p = S + (size_t)row * SLEN;
    const int L = q + 1;
    const int t = threadIdx.x;

    float v[8];
    float mx = -INFINITY;
#pragma unroll
    for (int i = 0; i < 8; i++) {
        int idx = t + i * 256;
        v[i] = (idx < L) ? p[idx] * scale : -INFINITY;
        mx = fmaxf(mx, v[i]);
    }

    __shared__ float redm[8];
    __shared__ float reds[8];

#pragma unroll
    for (int o = 16; o; o >>= 1) mx = fmaxf(mx, __shfl_xor_sync(0xFFFFFFFFu, mx, o));
    if ((t & 31) == 0) redm[t >> 5] = mx;
    __syncthreads();
    float m = redm[0];
#pragma unroll
    for (int i = 1; i < 8; i++) m = fmaxf(m, redm[i]);

    float s = 0.0f;
#pragma unroll
    for (int i = 0; i < 8; i++) {
        float e = __expf(v[i] - m);
        v[i] = e;
        s += e;
    }
#pragma unroll
    for (int o = 16; o; o >>= 1) s += __shfl_xor_sync(0xFFFFFFFFu, s, o);
    if ((t & 31) == 0) reds[t >> 5] = s;
    __syncthreads();
    float tot = 0.0f;
#pragma unroll
    for (int i = 0; i < 8; i++) tot += reds[i];
    const float inv = 1.0f / tot;

    fp16* ph = P + (size_t)row * SLEN;
    const int pad = (L + 127) & ~127;
#pragma unroll
    for (int i = 0; i < 8; i++) {
        int idx = t + i * 256;
        if (idx < L)        ph[idx] = __float2half_rn(v[i] * inv);
        else if (idx < pad) ph[idx] = __float2half_rn(0.0f);
    }
}

// ---------------------------------------------------------------------------
extern "C" void kernel_launch(void* const* d_in, const int* in_sizes, int n_in,
                              void* d_out, int out_size)
{
    const float* x  = (const float*)d_in[0];
    const float* Wq = (const float*)d_in[1];
    const float* Wk = (const float*)d_in[2];
    const float* Wv = (const float*)d_in[3];
    float* out = (float*)d_out;
    (void)in_sizes; (void)n_in; (void)out_size;

    cudaFuncSetAttribute(gemm1h, cudaFuncAttributeMaxDynamicSharedMemorySize, SMEM_REQ);

    fp16 *X, *WT, *QK, *VT, *P;
    float *Sp;
    cudaGetSymbolAddress((void**)&X, g_X);
    cudaGetSymbolAddress((void**)&WT, g_WT);
    cudaGetSymbolAddress((void**)&QK, g_QK);
    cudaGetSymbolAddress((void**)&VT, g_VT);
    cudaGetSymbolAddress((void**)&Sp, g_S);
    cudaGetSymbolAddress((void**)&P, g_P);

    const size_t WSTRIDE = (size_t)DIN * DIN;

    // 1) convert x -> fp16
    convert_h<<<(NTOK * DIN / 4) / 256, 256>>>(x, X, NTOK * DIN / 4);

    // 2) transpose + convert all three weights -> fp16
    {
        dim3 g(DIN / 32, DIN / 32, 3), b(32, 8);
        transpose3_h<<<g, b>>>(Wq, Wk, Wv, WT);
    }

    // 3) merged QK projection: A = X, B = [Wq^T;Wk^T] -> fp16, ldc=2048
    {
        dim3 g(2 * DIN / BN, NTOK / BM, 1);   // 8 x 128
        gemm1h<<<g, 128, SMEM_REQ>>>(X, WT,
                                     DIN, DIN, DIN, 0, 0, 0,
                                     nullptr, QK, 2 * DIN, 2, 0);
    }

    // 4) V^T projection: A = Wv^T, B = X -> fp16
    {
        dim3 g(NTOK / BN, DIN / BM, 1);   // 32 x 16
        gemm1h<<<g, 128, SMEM_REQ>>>(WT + 2 * WSTRIDE, X,
                                     DIN, DIN, DIN, 0, 0, 0,
                                     nullptr, VT, NTOK, 2, 0);
    }

    // 5) scores: A = Q, B = K (cols 1024..2047), causal skip, fp32 out
    {
        dim3 g(SLEN / BN, SLEN / BM, BATCH);   // 8 x 32 x 4
        gemm1h<<<g, 128, SMEM_REQ>>>(QK, QK + DIN,
                                     DIN, 2 * DIN, 2 * DIN,
                                     (long long)SLEN * 2 * DIN, (long long)SLEN * 2 * DIN,
                                     (long long)SLEN * SLEN,
                                     Sp, nullptr, SLEN, 0, 1);
    }

    // 6) softmax -> fp16 P (pad to 128)
    softmax_h<<<BATCH * SLEN, 256>>>(Sp, P, 0.03125f);

    // 7) PV: A = P, B = V^T, k-bound + remap, fp32 out
    {
        dim3 g(DIN / BN, SLEN / BM, BATCH);    // 4 x 32 x 4
        gemm1h<<<g, 128, SMEM_REQ>>>(P, VT,
                                     SLEN, SLEN, NTOK,
                                     (long long)SLEN * SLEN, (long long)SLEN,
                                     (long long)SLEN * DIN,
                                     out, nullptr, DIN, 0, 3);
    }
}

// round 16
// speedup vs baseline: 1.0622x; 1.0622x over previous
#include <cuda_runtime.h>
#include <cuda_fp16.h>
#include <cstdint>
#include <cstddef>

typedef __half fp16;

#define BATCH 4
#define SLEN  2048
#define DIN   1024
#define NTOK  (BATCH*SLEN)

// CTA 64x128x64, 4 warps (2x2), warp 32x64, 1-pass fp16, 3-stage pipe, 3 CTAs/SM
#define BM 64
#define BN 128
#define BK 64
#define A_BYTES (64*128)            // 8KB
#define B_BYTES (128*128)           // 16KB
#define STAGE (A_BYTES + B_BYTES)   // 24KB/stage
#define NSTAGE 3
#define OFF_A 0
#define OFF_B A_BYTES
#define SMEM_REQ (1024 + NSTAGE*STAGE)   // ~73.7KB -> 3 CTAs/SM

// ---------------- scratch (device globals; no allocs allowed) ----------------
__device__ fp16 g_X[(size_t)NTOK*DIN];        // X fp16
__device__ fp16 g_WT[3][(size_t)DIN*DIN];     // W^T fp16; [0],[1] contiguous = QK merged B
__device__ fp16 g_QK[(size_t)NTOK*2*DIN];     // cols 0..1023=Q, 1024..2047=K
__device__ fp16 g_VT[(size_t)DIN*NTOK];       // V^T: [e][b*S+s]
__device__ float g_S[(size_t)BATCH*SLEN*SLEN];    // raw scores (unscaled)
__device__ fp16 g_P[(size_t)BATCH*SLEN*SLEN];     // softmax weights (zero-padded to 128)

// ---------------- helpers ----------------
__device__ __forceinline__ uint32_t smem_u32(const void* p) {
    return (uint32_t)__cvta_generic_to_shared(p);
}
#define CP_COMMIT() asm volatile("cp.async.commit_group;\n" ::: "memory")
#define CP_WAIT2()  asm volatile("cp.async.wait_group 2;\n" ::: "memory")
#define CP_WAIT0()  asm volatile("cp.async.wait_group 0;\n" ::: "memory")

__device__ __forceinline__ void ldsm4(uint32_t* r, uint32_t addr) {
    asm volatile("ldmatrix.sync.aligned.m8n8.x4.shared.b16 {%0,%1,%2,%3}, [%4];"
        : "=r"(r[0]), "=r"(r[1]), "=r"(r[2]), "=r"(r[3]) : "r"(addr));
}
__device__ __forceinline__ void mma_f16(float* d, const uint32_t* a, const uint32_t* b) {
    asm volatile(
        "mma.sync.aligned.m16n8k16.row.col.f32.f16.f16.f32 "
        "{%0,%1,%2,%3}, {%4,%5,%6,%7}, {%8,%9}, {%0,%1,%2,%3};"
        : "+f"(d[0]), "+f"(d[1]), "+f"(d[2]), "+f"(d[3])
        : "r"(a[0]), "r"(a[1]), "r"(a[2]), "r"(a[3]), "r"(b[0]), "r"(b[1]));
}

// cp.async a [ROWS x 64 fp16] tile (128B rows) into swizzled smem; 128 threads
template<int ROWS>
__device__ __forceinline__ void load_panel(const fp16* __restrict__ g, int ld,
                                           int row0, int k0, uint32_t sdst, int tid)
{
#pragma unroll
    for (int c = tid; c < ROWS * 8; c += 128) {
        int r = c >> 3, col = c & 7;
        const void* src = (const void*)(g + (size_t)(row0 + r) * ld + k0 + col * 8);
        uint32_t dst = sdst + ((uint32_t)r << 7) + ((uint32_t)(col ^ (r & 7)) << 4);
        asm volatile("cp.async.cg.shared.global [%0], [%1], 16;\n" :: "r"(dst), "l"(src));
    }
}

__device__ __forceinline__ void load_stage(const fp16* A, const fp16* B, int lda, int ldb,
                                           int m0, int n0, int k0, uint32_t sb, int tid)
{
    load_panel<BM>(A, lda, m0, k0, sb + OFF_A, tid);
    load_panel<BN>(B, ldb, n0, k0, sb + OFF_B, tid);
}

// ---------------------------------------------------------------------------
// fp16 1-pass warp-MMA GEMM: D[m][n] = sum_k A[m][k]*B[n][k]
// mode 0: fp32 output; mode 2: fp16 output
// causal 0: none; 1: skip tiles above diagonal (scores);
//        3: kEnd=(by+1)*BM + load-balance remap of by (PV)
// 128 threads (2m x 2n warps, warp 32x64), 3-stage cp.async pipeline,
// register-level fragment double-buffering. Target 3 CTAs/SM (reg cap 170).
// ---------------------------------------------------------------------------
__global__ void __launch_bounds__(128, 3)
gemm1h(const fp16* __restrict__ A, const fp16* __restrict__ B,
       int K, int lda, int ldb,
       long long sAz, long long sBz, long long sCz,
       float* __restrict__ Cf, fp16* __restrict__ Ch,
       int ldc, int mode, int causal)
{
    const int bx = blockIdx.x, z = blockIdx.z;
    int by = blockIdx.y;
    if (causal == 3) {
        const int n = gridDim.y;
        by = (by & 1) ? (n - 1 - (by >> 1)) : (by >> 1);
    }
    const int m0 = by * BM, n0 = bx * BN;
    if (causal == 1 && n0 > m0 + (BM - 1)) return;

    const int kEnd = (causal == 3) ? (by + 1) * BM : K;
    const int nit = kEnd / BK;

    const fp16* Ap = A + (size_t)z * sAz;
    const fp16* Bp = B + (size_t)z * sBz;

    extern __shared__ char smem_raw[];
    const uint32_t sbase = (smem_u32(smem_raw) + 1023u) & ~1023u;

    const int tid = threadIdx.x;
    const int wid = tid >> 5, lid = tid & 31;
    const int warp_m = wid >> 1;        // 0..1 (32 rows each)
    const int warp_n = wid & 1;         // 0..1 (64 cols each)

    float acc[2][8][4];
#pragma unroll
    for (int i = 0; i < 2; i++)
#pragma unroll
        for (int j = 0; j < 8; j++)
#pragma unroll
            for (int q = 0; q < 4; q++) acc[i][j][q] = 0.0f;

    const int a_row_base = warp_m * 32 + (lid & 15);
    const int a_chalf = lid >> 4;
    const int b_row_base = warp_n * 64 + (lid >> 4) * 8 + (lid & 7);
    const int b_chalf = (lid >> 3) & 1;

    // prologue: stages 0 and 1 (always 2 commits for uniform group counting)
    load_stage(Ap, Bp, lda, ldb, m0, n0, 0, sbase, tid);
    CP_COMMIT();
    if (nit > 1) load_stage(Ap, Bp, lda, ldb, m0, n0, BK, sbase + STAGE, tid);
    CP_COMMIT();

    uint32_t ah[2][2][4];               // [buf][im][4]
    uint32_t bh[2][4][4];               // [buf][jn][4]

    int sidx = 0;                       // smem stage index of iteration it
    for (int it = 0; it < nit; it++) {
        // issue stage it+2 into the buffer being vacated (uniform commit)
        if (it + 2 < nit) {
            int snext = sidx + 2; if (snext >= NSTAGE) snext -= NSTAGE;
            load_stage(Ap, Bp, lda, ldb, m0, n0, (it + 2) * BK,
                       sbase + (uint32_t)snext * STAGE, tid);
        }
        CP_COMMIT();
        CP_WAIT2();                     // stage `it` complete (<=2 younger pending)
        __syncthreads();

        const uint32_t sb = sbase + (uint32_t)sidx * STAGE;

        // preload kk=0 fragments
#pragma unroll
        for (int im = 0; im < 2; im++) {
            const int row = a_row_base + im * 16;
            const uint32_t off = ((uint32_t)row << 7) + ((uint32_t)(a_chalf ^ (row & 7)) << 4);
            ldsm4(ah[0][im], sb + OFF_A + off);
        }
#pragma unroll
        for (int jn = 0; jn < 4; jn++) {
            const int n = b_row_base + jn * 16;
            const uint32_t off = ((uint32_t)n << 7) + ((uint32_t)(b_chalf ^ (n & 7)) << 4);
            ldsm4(bh[0][jn], sb + OFF_B + off);
        }

#pragma unroll
        for (int kk = 0; kk < 4; kk++) {
            const int cur = kk & 1, nxt = cur ^ 1;
            if (kk < 3) {   // prefetch kk+1 fragments during kk's MMAs
#pragma unroll
                for (int im = 0; im < 2; im++) {
                    const int row = a_row_base + im * 16;
                    const int c16 = (kk + 1) * 2 + a_chalf;
                    const uint32_t off = ((uint32_t)row << 7) + ((uint32_t)(c16 ^ (row & 7)) << 4);
                    ldsm4(ah[nxt][im], sb + OFF_A + off);
                }
#pragma unroll
                for (int jn = 0; jn < 4; jn++) {
                    const int n = b_row_base + jn * 16;
                    const int c16 = (kk + 1) * 2 + b_chalf;
                    const uint32_t off = ((uint32_t)n << 7) + ((uint32_t)(c16 ^ (n & 7)) << 4);
                    ldsm4(bh[nxt][jn], sb + OFF_B + off);
                }
            }
#pragma unroll
            for (int jn = 0; jn < 4; jn++) {
#pragma unroll
                for (int im = 0; im < 2; im++) {
#pragma unroll
                    for (int h = 0; h < 2; h++) {
                        mma_f16(acc[im][jn * 2 + h], ah[cur][im], bh[cur][jn] + 2 * h);
                    }
                }
            }
        }
        __syncthreads();
        if (++sidx == NSTAGE) sidx = 0;
    }

    // epilogue
    const int tq = lid >> 2;
    const int tr = lid & 3;
    const size_t cbase = (size_t)z * (size_t)sCz;
#pragma unroll
    for (int im = 0; im < 2; im++) {
#pragma unroll
        for (int j = 0; j < 8; j++) {
            const int r0 = m0 + warp_m * 32 + im * 16 + tq;
            const int c0 = n0 + warp_n * 64 + j * 8 + tr * 2;
            const float* d = acc[im][j];
            if (mode == 0) {
                *(float2*)(Cf + cbase + (size_t)r0 * ldc + c0)       = make_float2(d[0], d[1]);
                *(float2*)(Cf + cbase + (size_t)(r0 + 8) * ldc + c0) = make_float2(d[2], d[3]);
            } else {
#pragma unroll
                for (int rr = 0; rr < 2; rr++) {
                    __half2 hv;
                    hv.x = __float2half_rn(d[2 * rr]);
                    hv.y = __float2half_rn(d[2 * rr + 1]);
                    const size_t o = cbase + (size_t)(r0 + 8 * rr) * ldc + c0;
                    *(uint32_t*)(Ch + o) = *(uint32_t*)&hv;
                }
            }
        }
    }
}

// ---------------------------------------------------------------------------
// fp32 -> fp16 convert, elementwise (4 per thread)
// ---------------------------------------------------------------------------
__global__ void __launch_bounds__(256)
convert_h(const float* __restrict__ x, fp16* __restrict__ h16, int n4)
{
    int i = blockIdx.x * 256 + threadIdx.x;
    if (i >= n4) return;
    float4 v = ((const float4*)x)[i];
    fp16 h[4];
    h[0] = __float2half_rn(v.x);
    h[1] = __float2half_rn(v.y);
    h[2] = __float2half_rn(v.z);
    h[3] = __float2half_rn(v.w);
    ((uint2*)h16)[i] = *(uint2*)h;
}

// ---------------------------------------------------------------------------
// All three weights: W [DIN x DIN] fp32 -> W^T fp16 (z selects matrix)
// ---------------------------------------------------------------------------
__global__ void __launch_bounds__(256)
transpose3_h(const float* __restrict__ W0, const float* __restrict__ W1,
             const float* __restrict__ W2, fp16* __restrict__ T)
{
    const int zz = blockIdx.z;
    const float* W = (zz == 0) ? W0 : (zz == 1) ? W1 : W2;
    const size_t zoff = (size_t)zz * DIN * DIN;

    __shared__ float t[32][33];
    const int bx = blockIdx.x * 32, by = blockIdx.y * 32;
    const int x = threadIdx.x, y = threadIdx.y;
#pragma unroll
    for (int i = 0; i < 32; i += 8)
        t[y + i][x] = W[(size_t)(by + y + i) * DIN + bx + x];
    __syncthreads();
#pragma unroll
    for (int i = 0; i < 32; i += 8)
        T[zoff + (size_t)(bx + y + i) * DIN + by + x] = __float2half_rn(t[x][y + i]);
}

// ---------------------------------------------------------------------------
// Softmax over k<=q of scale*S, emit fp16 P, zero-pad to 128 boundary
// ---------------------------------------------------------------------------
__global__ void __launch_bounds__(256)
softmax_h(const float* __restrict__ S, fp16* __restrict__ P, float scale)
{
    const int row = blockIdx.x;
    const int q = row & (SLEN - 1);
    const float* p = S + (size_t)row * SLEN;
    const int L = q + 1;
    const int t = threadIdx.x;

    float v[8];
    float mx = -INFINITY;
#pragma unroll
    for (int i = 0; i < 8; i++) {
        int idx = t + i * 256;
        v[i] = (idx < L) ? p[idx] * scale : -INFINITY;
        mx = fmaxf(mx, v[i]);
    }

    __shared__ float redm[8];
    __shared__ float reds[8];

#pragma unroll
    for (int o = 16; o; o >>= 1) mx = fmaxf(mx, __shfl_xor_sync(0xFFFFFFFFu, mx, o));
    if ((t & 31) == 0) redm[t >> 5] = mx;
    __syncthreads();
    float m = redm[0];
#pragma unroll
    for (int i = 1; i < 8; i++) m = fmaxf(m, redm[i]);

    float s = 0.0f;
#pragma unroll
    for (int i = 0; i < 8; i++) {
        float e = __expf(v[i] - m);
        v[i] = e;
        s += e;
    }
#pragma unroll
    for (int o = 16; o; o >>= 1) s += __shfl_xor_sync(0xFFFFFFFFu, s, o);
    if ((t & 31) == 0) reds[t >> 5] = s;
    __syncthreads();
    float tot = 0.0f;
#pragma unroll
    for (int i = 0; i < 8; i++) tot += reds[i];
    const float inv = 1.0f / tot;

    fp16* ph = P + (size_t)row * SLEN;
    const int pad = (L + 127) & ~127;
#pragma unroll
    for (int i = 0; i < 8; i++) {
        int idx = t + i * 256;
        if (idx < L)        ph[idx] = __float2half_rn(v[i] * inv);
        else if (idx < pad) ph[idx] = __float2half_rn(0.0f);
    }
}

// ---------------------------------------------------------------------------
extern "C" void kernel_launch(void* const* d_in, const int* in_sizes, int n_in,
                              void* d_out, int out_size)
{
    const float* x  = (const float*)d_in[0];
    const float* Wq = (const float*)d_in[1];
    const float* Wk = (const float*)d_in[2];
    const float* Wv = (const float*)d_in[3];
    float* out = (float*)d_out;
    (void)in_sizes; (void)n_in; (void)out_size;

    cudaFuncSetAttribute(gemm1h, cudaFuncAttributeMaxDynamicSharedMemorySize, SMEM_REQ);

    fp16 *X, *WT, *QK, *VT, *P;
    float *Sp;
    cudaGetSymbolAddress((void**)&X, g_X);
    cudaGetSymbolAddress((void**)&WT, g_WT);
    cudaGetSymbolAddress((void**)&QK, g_QK);
    cudaGetSymbolAddress((void**)&VT, g_VT);
    cudaGetSymbolAddress((void**)&Sp, g_S);
    cudaGetSymbolAddress((void**)&P, g_P);

    const size_t WSTRIDE = (size_t)DIN * DIN;

    // 1) convert x -> fp16
    convert_h<<<(NTOK * DIN / 4) / 256, 256>>>(x, X, NTOK * DIN / 4);

    // 2) transpose + convert all three weights -> fp16
    {
        dim3 g(DIN / 32, DIN / 32, 3), b(32, 8);
        transpose3_h<<<g, b>>>(Wq, Wk, Wv, WT);
    }

    // 3) merged QK projection: A = X, B = [Wq^T;Wk^T] -> fp16, ldc=2048
    {
        dim3 g(2 * DIN / BN, NTOK / BM, 1);   // 16 x 128
        gemm1h<<<g, 128, SMEM_REQ>>>(X, WT,
                                     DIN, DIN, DIN, 0, 0, 0,
                                     nullptr, QK, 2 * DIN, 2, 0);
    }

    // 4) V^T projection: A = Wv^T, B = X -> fp16
    {
        dim3 g(NTOK / BN, DIN / BM, 1);   // 64 x 16
        gemm1h<<<g, 128, SMEM_REQ>>>(WT + 2 * WSTRIDE, X,
                                     DIN, DIN, DIN, 0, 0, 0,
                                     nullptr, VT, NTOK, 2, 0);
    }

    // 5) scores: A = Q, B = K (cols 1024..2047), causal skip, fp32 out
    {
        dim3 g(SLEN / BN, SLEN / BM, BATCH);   // 16 x 32 x 4
        gemm1h<<<g, 128, SMEM_REQ>>>(QK, QK + DIN,
                                     DIN, 2 * DIN, 2 * DIN,
                                     (long long)SLEN * 2 * DIN, (long long)SLEN * 2 * DIN,
                                     (long long)SLEN * SLEN,
                                     Sp, nullptr, SLEN, 0, 1);
    }

    // 6) softmax -> fp16 P (pad to 128)
    softmax_h<<<BATCH * SLEN, 256>>>(Sp, P, 0.03125f);

    // 7) PV: A = P, B = V^T, k-bound + remap, fp32 out
    {
        dim3 g(DIN / BN, SLEN / BM, BATCH);    // 8 x 32 x 4
        gemm1h<<<g, 128, SMEM_REQ>>>(P, VT,
                                     SLEN, SLEN, NTOK,
                                     (long long)SLEN * SLEN, (long long)SLEN,
                                     (long long)SLEN * DIN,
                                     out, nullptr, DIN, 0, 3);
    }
}